// round 7
// baseline (speedup 1.0000x reference)
#include <cuda_runtime.h>
#include <cuda_bf16.h>
#include <cstdint>

#define NS 64
#define ND 32
#define NB 32
#define NT 1024
#define NF 64
#define NC 128
#define L2E 1.4426950408889634f
#define LN2D 0.6931471805599453

// ---------------- scratch (static device globals; no allocation) ----------------
__device__ float g_h[10240];            // hidden activations: [0:4096) A, [4096:6144) D, [6144:10240) E
__device__ float g_dA[4096];
__device__ float g_dD[2048];
__device__ float g_dE[4096];
__device__ float g_AT[NS * NS];         // A transposed: g_AT[s_to*64 + s_from] (linear probs)
__device__ float g_DurT[ND * NS];       // linear duration probs [d0][s] (d0 = d-1)
__device__ float g_invT[NF * NS];
__device__ float g_W2T[NF * NS];
__device__ float g_cst[NS];
__device__ float g_z[(size_t)NB * NT * NS + 8 * NS];    // 2^(logB - c), padded 8 steps
__device__ float g_c[NB * NT];                          // per-(b,t) max_s base-2 logB
__device__ double g_csum[NB];                           // sum_t c

// ---------------- fast math helpers ----------------
__device__ __forceinline__ float ex2f(float x) {
    float y; asm("ex2.approx.ftz.f32 %0, %1;" : "=f"(y) : "f"(x)); return y;
}
__device__ __forceinline__ float lg2f(float x) {
    float y; asm("lg2.approx.f32 %0, %1;" : "=f"(y) : "f"(x)); return y;
}

// ---------------- fused first-layer matvecs: h = tanh(W1 @ ctx + b1), all 3 MLPs ---------------
__global__ void lin1_kernel(const float* __restrict__ ctx,
                            const float* __restrict__ wA, const float* __restrict__ bA,
                            const float* __restrict__ wD, const float* __restrict__ bD,
                            const float* __restrict__ wE, const float* __restrict__ bE)
{
    __shared__ float sin_[NC];
    if (threadIdx.x < NC) sin_[threadIdx.x] = ctx[threadIdx.x];
    __syncthreads();

    int row  = (int)((blockIdx.x * blockDim.x + threadIdx.x) >> 5);
    int lane = threadIdx.x & 31;

    const float* W; const float* bias; float* out; int r;
    if (row < 4096)      { W = wA; bias = bA; out = g_h;        r = row; }
    else if (row < 6144) { W = wD; bias = bD; out = g_h + 4096; r = row - 4096; }
    else                 { W = wE; bias = bE; out = g_h + 6144; r = row - 6144; }

    float4 w = ((const float4*)(W + (size_t)r * NC))[lane];
    float4 v = ((const float4*)sin_)[lane];
    float acc = w.x * v.x;
    acc = fmaf(w.y, v.y, acc); acc = fmaf(w.z, v.z, acc); acc = fmaf(w.w, v.w, acc);
#pragma unroll
    for (int o = 16; o; o >>= 1) acc += __shfl_xor_sync(0xffffffffu, acc, o);
    if (lane == 0) out[r] = tanhf(acc + bias[r]);
}

// ---------------- fused second-layer matvecs: d = W2 @ h + b2, all 3 MLPs ----------------
__global__ void lin2_kernel(const float* __restrict__ wA, const float* __restrict__ bA,
                            const float* __restrict__ wD, const float* __restrict__ bD,
                            const float* __restrict__ wE, const float* __restrict__ bE)
{
    __shared__ float sin_[4096];
    int row0 = blockIdx.x * 8;

    const float* in; const float* W; const float* bias; float* out; int n_in, base;
    if (row0 < 4096)      { in = g_h;        n_in = 4096; W = wA; bias = bA; out = g_dA; base = 0; }
    else if (row0 < 6144) { in = g_h + 4096; n_in = 2048; W = wD; bias = bD; out = g_dD; base = 4096; }
    else                  { in = g_h + 6144; n_in = 4096; W = wE; bias = bE; out = g_dE; base = 6144; }

    for (int i = threadIdx.x; i < n_in; i += blockDim.x) sin_[i] = in[i];
    __syncthreads();

    int r    = row0 - base + (int)(threadIdx.x >> 5);
    int lane = threadIdx.x & 31;
    const float4* Wr = (const float4*)(W + (size_t)r * n_in);
    const float4* vr = (const float4*)sin_;
    int n4 = n_in >> 2;

    float a0 = 0.f, a1 = 0.f, a2 = 0.f, a3 = 0.f;
    for (int k = lane; k < n4; k += 128) {
        float4 w0 = Wr[k], w1 = Wr[k + 32], w2 = Wr[k + 64], w3 = Wr[k + 96];
        float4 v0 = vr[k], v1 = vr[k + 32], v2 = vr[k + 64], v3 = vr[k + 96];
        a0 = fmaf(w0.x, v0.x, a0); a0 = fmaf(w0.y, v0.y, a0);
        a0 = fmaf(w0.z, v0.z, a0); a0 = fmaf(w0.w, v0.w, a0);
        a1 = fmaf(w1.x, v1.x, a1); a1 = fmaf(w1.y, v1.y, a1);
        a1 = fmaf(w1.z, v1.z, a1); a1 = fmaf(w1.w, v1.w, a1);
        a2 = fmaf(w2.x, v2.x, a2); a2 = fmaf(w2.y, v2.y, a2);
        a2 = fmaf(w2.z, v2.z, a2); a2 = fmaf(w2.w, v2.w, a2);
        a3 = fmaf(w3.x, v3.x, a3); a3 = fmaf(w3.y, v3.y, a3);
        a3 = fmaf(w3.z, v3.z, a3); a3 = fmaf(w3.w, v3.w, a3);
    }
    float acc = (a0 + a1) + (a2 + a3);
#pragma unroll
    for (int o = 16; o; o >>= 1) acc += __shfl_xor_sync(0xffffffffu, acc, o);
    if (lane == 0) out[r] = acc + bias[r];
}

// ---------------- postprocess: softmaxes + emission params (1 block per state s, 32 thr) --------
__global__ void post_kernel(const float* __restrict__ A_logits, const float* __restrict__ D_logits,
                            const float* __restrict__ mu, const float* __restrict__ log_var)
{
    int s = blockIdx.x, lane = threadIdx.x;

    int i0 = s * NS + lane;
    float z0 = A_logits[i0]      + 0.1f * tanhf(g_dA[i0]);
    float z1 = A_logits[i0 + 32] + 0.1f * tanhf(g_dA[i0 + 32]);
    float m = fmaxf(z0, z1);
#pragma unroll
    for (int o = 16; o; o >>= 1) m = fmaxf(m, __shfl_xor_sync(0xffffffffu, m, o));
    float e0 = expf(z0 - m), e1 = expf(z1 - m);
    float ss = e0 + e1;
#pragma unroll
    for (int o = 16; o; o >>= 1) ss += __shfl_xor_sync(0xffffffffu, ss, o);
    float inv_ss = 1.f / ss;
    g_AT[lane * NS + s]        = e0 * inv_ss;
    g_AT[(lane + 32) * NS + s] = e1 * inv_ss;

    int id = s * ND + lane;
    float zd = D_logits[id] + 0.1f * tanhf(g_dD[id]);
    float md = zd;
#pragma unroll
    for (int o = 16; o; o >>= 1) md = fmaxf(md, __shfl_xor_sync(0xffffffffu, md, o));
    float ed = expf(zd - md);
    float sd = ed;
#pragma unroll
    for (int o = 16; o; o >>= 1) sd += __shfl_xor_sync(0xffffffffu, sd, o);
    g_DurT[lane * NS + s] = ed / sd;

    float cp = 0.f;
#pragma unroll
    for (int half = 0; half < 2; half++) {
        int f = lane + half * 32;
        int ie = s * NF + f;
        float mc = mu[ie] + 0.1f * tanhf(g_dE[ie]);
        float lv = log_var[ie];
        float sp = (lv > 20.f) ? lv : log1pf(expf(lv));
        float v = sp + 0.001f;
        float iv = 1.f / v;
        g_invT[f * NS + s] = iv;
        g_W2T[f * NS + s] = 2.f * mc * iv;
        cp += mc * mc * iv + logf(v);
    }
#pragma unroll
    for (int o = 16; o; o >>= 1) cp += __shfl_xor_sync(0xffffffffu, cp, o);
    if (lane == 0) g_cst[s] = cp + (float)NF * 1.8378770664093453f;
}

// ---------------- fused emission + z-prep: z[bt][s] = 2^(logB - c), c = row max ----------------
// f-loop blocked by 4 with float4 broadcast x loads: 256 LDS/thread (was 640).
__global__ void logbz_kernel(const float* __restrict__ x)
{
    __shared__ float xs[32 * 64];        // x tile; reused as logB buffer after conv
    __shared__ float ivs[64 * 64];
    __shared__ float w2s[64 * 64];
    __shared__ float csts[64];
    int tid = threadIdx.x;
    size_t bt0 = (size_t)blockIdx.x * 32;

    for (int i = tid; i < 4096; i += 256) {
        ivs[i] = g_invT[i];
        w2s[i] = g_W2T[i];
    }
    for (int i = tid; i < 2048; i += 256) xs[i] = x[bt0 * NF + i];
    if (tid < 64) csts[tid] = g_cst[tid];
    __syncthreads();

    int s = tid & 63, rg = tid >> 6;
    float acc[8];
#pragma unroll
    for (int k = 0; k < 8; k++) acc[k] = 0.f;

    const float4* xs4 = (const float4*)xs;
#pragma unroll 2
    for (int f4 = 0; f4 < 16; f4++) {
        float iv0 = ivs[(4 * f4 + 0) * 64 + s], w20 = w2s[(4 * f4 + 0) * 64 + s];
        float iv1 = ivs[(4 * f4 + 1) * 64 + s], w21 = w2s[(4 * f4 + 1) * 64 + s];
        float iv2 = ivs[(4 * f4 + 2) * 64 + s], w22 = w2s[(4 * f4 + 2) * 64 + s];
        float iv3 = ivs[(4 * f4 + 3) * 64 + s], w23 = w2s[(4 * f4 + 3) * 64 + s];
#pragma unroll
        for (int k = 0; k < 8; k++) {
            float4 xv = xs4[(rg * 8 + k) * 16 + f4];
            acc[k] = fmaf(xv.x, fmaf(iv0, xv.x, -w20), acc[k]);
            acc[k] = fmaf(xv.y, fmaf(iv1, xv.y, -w21), acc[k]);
            acc[k] = fmaf(xv.z, fmaf(iv2, xv.z, -w22), acc[k]);
            acc[k] = fmaf(xv.w, fmaf(iv3, xv.w, -w23), acc[k]);
        }
    }
    float c = csts[s];
    const float sc = -0.5f * L2E;
    float lb[8];
#pragma unroll
    for (int k = 0; k < 8; k++) lb[k] = (acc[k] + c) * sc;

    __syncthreads();
#pragma unroll
    for (int k = 0; k < 8; k++) xs[(rg * 8 + k) * 64 + s] = lb[k];
    __syncthreads();

    int w = tid >> 5, lane = tid & 31;
#pragma unroll
    for (int j = 0; j < 4; j++) {
        int r = 4 * w + j;
        float v0 = xs[r * 64 + lane];
        float v1 = xs[r * 64 + 32 + lane];
        float m = fmaxf(v0, v1);
#pragma unroll
        for (int o = 16; o; o >>= 1) m = fmaxf(m, __shfl_xor_sync(0xffffffffu, m, o));
        size_t base = (bt0 + r) * NS;
        g_z[base + lane]      = ex2f(v0 - m);
        g_z[base + lane + 32] = ex2f(v1 - m);
        if (lane == 0) g_c[bt0 + r] = m;
    }
}

// ---------------- per-batch sum of c (double) ----------------
__global__ void csum_kernel()
{
    int b = (int)(threadIdx.x >> 5);
    int lane = threadIdx.x & 31;
    double s = 0.0;
    for (int t = lane; t < NT; t += 32) s += (double)g_c[b * NT + t];
#pragma unroll
    for (int o = 16; o; o >>= 1) s += __shfl_xor_sync(0xffffffffu, s, o);
    if (lane == 0) g_csum[b] = s;
}

// ---------------- linear-domain HSMM scan: one CTA (256 thr) per batch ----------------
// tid = s*4 + p : state s (0..63), partition p (0..3) owns durations d = 8p+1..8p+8.
// Each partition keeps 8 ring slots in static registers; the t-loop is unrolled x8 so
// slot roles rotate without register movement. Per step:
//   ring *= z_t[s]*rho ; acc_p = sum Dur*ring ; quad-reduce acc (shfl 1,2);
//   warp-max of acc -> mod-3 smem ring (controller, eta=1/2, lag-2 as in R5);
//   barrier ; matvec q[s] = AT[s][:] . acc[:] in packed fma.rn.f32x2 (4-way split,
//   quad-reduced) ; slot migration p->p+1 via one shfl_up ; insert q (p0).
// Exact scale ledger: pend = -lg2(rho) accumulated (tid 0, double) when rho applied.
__global__ void __launch_bounds__(256, 1) scan_kernel(float* __restrict__ out)
{
    __shared__ __align__(16) float sm_acc[2][NS];
    __shared__ __align__(16) float sm_wmax[3][8];
    __shared__ float sm_part[8];

    int b = blockIdx.x;
    int tid = threadIdx.x;
    int s = tid >> 2, p = tid & 3, lane = tid & 31, wid = tid >> 5;

    // A columns for this (s, p): AT[s][p*16 .. p*16+15], packed as 8 x f32x2
    unsigned long long Ac[8];
    {
        const ulonglong2* ap = (const ulonglong2*)(g_AT + (size_t)s * NS + p * 16);
#pragma unroll
        for (int j = 0; j < 4; j++) { ulonglong2 v = ap[j]; Ac[2 * j] = v.x; Ac[2 * j + 1] = v.y; }
    }
    float durk[8];                         // durk[a] = Dur[d = 8p + a + 1][s]
#pragma unroll
    for (int a = 0; a < 8; a++) durk[a] = g_DurT[(8 * p + a) * NS + s];

    float W[8];
#pragma unroll
    for (int j = 0; j < 8; j++) W[j] = 0.f;
    if (p == 0) W[7] = 0.015625f;          // pi seed: age 1 (d=1) at t=0, ages with shifts

    const float* zp = g_z + (size_t)b * NT * NS + s;
    float zq[8];
#pragma unroll
    for (int i = 0; i < 8; i++) zq[i] = zp[(size_t)i * NS];

    if (tid < 8) sm_wmax[2][tid] = 4294967296.0f;   // first controller read -> rho = 1
    float rho = 1.f, pend = 0.f;
    double rr = 0.0;
    float lastacc = 0.f;
    int wi = 0, ri = 2;                    // mod-3 write/read indices (write t%3, read (t-1)%3)
    __syncthreads();

    for (int t8 = 0; t8 < NT; t8 += 8) {
#pragma unroll
        for (int i = 0; i < 8; i++) {
            const int par = i & 1;
            if (tid == 0) rr += (double)pend;
            float mlt = zq[i] * rho;
            zq[i] = zp[(size_t)(t8 + i + 8) * NS];   // prefetch (padded)

            // ring scale + duration conv; coeff for slot j at sub-step i: durk[(i-1-j)&7]
            float a0 = 0.f, a1 = 0.f;
#pragma unroll
            for (int j = 0; j < 8; j++) {
                W[j] *= mlt;
                float cdur = durk[(i - 1 - j) & 7];
                if (j & 1) a1 = fmaf(cdur, W[j], a1);
                else       a0 = fmaf(cdur, W[j], a0);
            }
            float acc = a0 + a1;
            acc += __shfl_xor_sync(0xffffffffu, acc, 1);
            acc += __shfl_xor_sync(0xffffffffu, acc, 2);
            lastacc = acc;

            // warp max of acc (controller proxy), piggybacked on reduce tree
            float wm = acc;
            wm = fmaxf(wm, __shfl_xor_sync(0xffffffffu, wm, 4));
            wm = fmaxf(wm, __shfl_xor_sync(0xffffffffu, wm, 8));
            wm = fmaxf(wm, __shfl_xor_sync(0xffffffffu, wm, 16));
            if (lane == 0) sm_wmax[wi][wid] = wm;
            if (p == 0) sm_acc[par][s] = acc;
            __syncthreads();

            // controller: rho from wmax written last step (lag-2 total at application)
            float4 wa = *(const float4*)&sm_wmax[ri][0];
            float4 wb = *(const float4*)&sm_wmax[ri][4];
            float qmax = fmaxf(fmaxf(fmaxf(wa.x, wa.y), fmaxf(wa.z, wa.w)),
                               fmaxf(fmaxf(wb.x, wb.y), fmaxf(wb.z, wb.w)));
            qmax = fminf(fmaxf(qmax, 1e-30f), 1e30f);
            float hl = 0.5f * lg2f(qmax);
            rho  = ex2f(16.0f - hl);
            pend = hl - 16.0f;
            wi = (wi == 2) ? 0 : wi + 1;
            ri = (ri == 2) ? 0 : ri + 1;

            // matvec partial (16 states) in packed f32x2
            const ulonglong2* ap = (const ulonglong2*)&sm_acc[par][p * 16];
            unsigned long long qa = 0ull, qb = 0ull;
#pragma unroll
            for (int j = 0; j < 4; j++) {
                ulonglong2 v = ap[j];
                asm("fma.rn.f32x2 %0, %1, %2, %0;" : "+l"(qa) : "l"(Ac[2 * j]),     "l"(v.x));
                asm("fma.rn.f32x2 %0, %1, %2, %0;" : "+l"(qb) : "l"(Ac[2 * j + 1]), "l"(v.y));
            }
            unsigned int l0, h0, l1, h1;
            asm("mov.b64 {%0,%1}, %2;" : "=r"(l0), "=r"(h0) : "l"(qa));
            asm("mov.b64 {%0,%1}, %2;" : "=r"(l1), "=r"(h1) : "l"(qb));
            float q = (__uint_as_float(l0) + __uint_as_float(h0))
                    + (__uint_as_float(l1) + __uint_as_float(h1));
            q += __shfl_xor_sync(0xffffffffu, q, 1);
            q += __shfl_xor_sync(0xffffffffu, q, 2);

            // migration: slot i (age 8, post-mlt) leaves partition p -> p+1; p0 inserts q
            float outv = W[i];
            float inc = __shfl_up_sync(0xffffffffu, outv, 1);
            W[i] = (p == 0) ? q : inc;
        }
    }

    // out[b] = ln2 * ( lg2(sum_s acc_final) + csum + rr )
    float v = lastacc;
    v += __shfl_xor_sync(0xffffffffu, v, 4);
    v += __shfl_xor_sync(0xffffffffu, v, 8);
    v += __shfl_xor_sync(0xffffffffu, v, 16);
    if (lane == 0) sm_part[wid] = v;
    __syncthreads();
    if (tid == 0) {
        float tot = 0.f;
#pragma unroll
        for (int w = 0; w < 8; w++) tot += sm_part[w];
        double res = (double)lg2f(tot) + g_csum[b] + rr;
        out[b] = (float)(res * LN2D);
    }
}

// ---------------- host launcher (6 launches; scan is #6 for ncu -s 5 -c 1) -------------
extern "C" void kernel_launch(void* const* d_in, const int* in_sizes, int n_in,
                              void* d_out, int out_size)
{
    const float* x        = (const float*)d_in[0];
    const float* context  = (const float*)d_in[1];
    const float* A_logits = (const float*)d_in[2];
    const float* D_logits = (const float*)d_in[3];
    const float* mu       = (const float*)d_in[4];
    const float* log_var  = (const float*)d_in[5];
    const float* tA_w1 = (const float*)d_in[6],  *tA_b1 = (const float*)d_in[7];
    const float* tA_w2 = (const float*)d_in[8],  *tA_b2 = (const float*)d_in[9];
    const float* tD_w1 = (const float*)d_in[10], *tD_b1 = (const float*)d_in[11];
    const float* tD_w2 = (const float*)d_in[12], *tD_b2 = (const float*)d_in[13];
    const float* tE_w1 = (const float*)d_in[14], *tE_b1 = (const float*)d_in[15];
    const float* tE_w2 = (const float*)d_in[16], *tE_b2 = (const float*)d_in[17];

    lin1_kernel<<<1280, 256>>>(context, tA_w1, tA_b1, tD_w1, tD_b1, tE_w1, tE_b1);
    lin2_kernel<<<1280, 256>>>(tA_w2, tA_b2, tD_w2, tD_b2, tE_w2, tE_b2);
    post_kernel<<<NS, 32>>>(A_logits, D_logits, mu, log_var);
    logbz_kernel<<<(NB * NT) / 32, 256>>>(x);
    csum_kernel<<<1, 1024>>>();
    scan_kernel<<<NB, 256>>>((float*)d_out);
}